// round 1
// baseline (speedup 1.0000x reference)
#include <cuda_runtime.h>
#include <cuda_bf16.h>

// NeiAttention: fused  v = [rel|node] @ W1^T + b ;  alpha = softmax(x.v/sqrt(D)) ; out = alpha.v
// Shapes: B=512, N=32, S=16, EF=64, NF=D=128, K=192.
// One CTA = (batch b, chunk of 8 nodes) = 128 GEMM rows. Grid (4, 512), block 256.

#define B_DIM   512
#define N_DIM   32
#define S_DIM   16
#define EF_DIM  64
#define D_DIM   128
#define K_DIM   192

#define ASTRIDE 196   // A tile row stride (floats), padded vs 192
#define WSTRIDE 130   // W^T row stride (floats), padded vs 128 (even -> 8B aligned pairs)
#define VSTRIDE 133   // v tile row stride (floats), odd-ish pad -> conflict-free column walks

// dynamic smem layout in floats:
#define OFF_A   0                 // 128*196 = 25088 floats (reused as sV: 128*133 = 17024)
#define OFF_W   25088             // 192*130 = 24960
#define OFF_X   50048             // 8*128   = 1024
#define OFF_B   51072             // 128
#define OFF_AL  51200             // 128
#define OFF_E   51328             // 128
#define OFF_P   51456             // 256
#define SMEM_FLOATS 51712
#define SMEM_BYTES  (SMEM_FLOATS * 4)   // 206,848 B

__device__ __forceinline__ unsigned long long pack2(float a) {
    unsigned long long r;
    asm("mov.b64 %0, {%1, %1};" : "=l"(r) : "f"(a));
    return r;
}
__device__ __forceinline__ float2 unpack2(unsigned long long v) {
    float2 f;
    asm("mov.b64 {%0, %1}, %2;" : "=f"(f.x), "=f"(f.y) : "l"(v));
    return f;
}
__device__ __forceinline__ unsigned long long fma2(unsigned long long a,
                                                   unsigned long long b,
                                                   unsigned long long c) {
    unsigned long long d;
    asm("fma.rn.f32x2 %0, %1, %2, %3;" : "=l"(d) : "l"(a), "l"(b), "l"(c));
    return d;
}

__global__ __launch_bounds__(256, 1)
void nei_attention_kernel(const float* __restrict__ x,
                          const float* __restrict__ x_nei_rel,
                          const float* __restrict__ x_nei_node,
                          const float* __restrict__ W1_w,
                          const float* __restrict__ W1_b,
                          float* __restrict__ out)
{
    extern __shared__ float smem[];
    float* sA  = smem + OFF_A;   // A tile / later v tile
    float* sW  = smem + OFF_W;   // W^T: [k][d]
    float* sX  = smem + OFF_X;   // 8 node feature rows
    float* sB  = smem + OFF_B;
    float* sAl = smem + OFF_AL;
    float* sE  = smem + OFF_E;
    float* sP  = smem + OFF_P;

    const int b   = blockIdx.y;        // 0..511
    const int nc  = blockIdx.x;        // 0..3 (chunk of 8 nodes)
    const int tid = threadIdx.x;
    const int tx  = tid & 15;          // column group 0..15
    const int ty  = tid >> 4;          // row group 0..15

    // ---------------- stage inputs in SMEM ----------------
    // A tile rows: 128 rows of concat(rel[64] | node[128]) for global rows nc*128 .. +127
    {
        const float4* rel = (const float4*)(x_nei_rel + ((size_t)b * 512 + (size_t)nc * 128) * EF_DIM);
        #pragma unroll
        for (int idx = tid; idx < 128 * 16; idx += 256) {
            int r = idx >> 4, c = idx & 15;
            float4 v = rel[r * 16 + c];
            *(float4*)(sA + r * ASTRIDE + c * 4) = v;
        }
        const float4* nod = (const float4*)(x_nei_node + ((size_t)b * 512 + (size_t)nc * 128) * D_DIM);
        #pragma unroll
        for (int idx = tid; idx < 128 * 32; idx += 256) {
            int r = idx >> 5, c = idx & 31;
            float4 v = nod[r * 32 + c];
            *(float4*)(sA + r * ASTRIDE + 64 + c * 4) = v;
        }
        // W1_w is [128 d][192 k] row-major; store transposed sW[k][d]
        const float4* Wv = (const float4*)W1_w;
        for (int idx = tid; idx < (D_DIM * K_DIM) / 4; idx += 256) {
            int d  = idx / 48;
            int k4 = idx - d * 48;
            float4 w = Wv[idx];
            sW[(k4 * 4 + 0) * WSTRIDE + d] = w.x;
            sW[(k4 * 4 + 1) * WSTRIDE + d] = w.y;
            sW[(k4 * 4 + 2) * WSTRIDE + d] = w.z;
            sW[(k4 * 4 + 3) * WSTRIDE + d] = w.w;
        }
        const float4* xv = (const float4*)(x + ((size_t)b * N_DIM + (size_t)nc * 8) * D_DIM);
        for (int idx = tid; idx < (8 * D_DIM) / 4; idx += 256) {
            *(float4*)(sX + idx * 4) = xv[idx];
        }
        if (tid < 128) sB[tid] = W1_b[tid];
    }
    __syncthreads();

    // ---------------- GEMM: C[128][128] = A[128][192] * W^T ----------------
    // thread (tx,ty) owns rows (ty + 16*i), i<8 ; col pairs (2*tx + 32*j, +1), j<4
    unsigned long long acc[8][4];
    #pragma unroll
    for (int i = 0; i < 8; i++)
        #pragma unroll
        for (int j = 0; j < 4; j++) acc[i][j] = 0ull;

    #pragma unroll 4
    for (int k = 0; k < K_DIM; k++) {
        unsigned long long wv[4];
        const float* wrow = sW + k * WSTRIDE + 2 * tx;
        #pragma unroll
        for (int j = 0; j < 4; j++)
            wv[j] = *(const unsigned long long*)(wrow + 32 * j);
        const float* acol = sA + ty * ASTRIDE + k;
        #pragma unroll
        for (int i = 0; i < 8; i++) {
            unsigned long long ap = pack2(acol[16 * i * ASTRIDE]);
            #pragma unroll
            for (int j = 0; j < 4; j++)
                acc[i][j] = fma2(ap, wv[j], acc[i][j]);
        }
    }
    __syncthreads();   // done reading sA -> safe to overwrite with v

    // bias add + store v tile into SMEM (overlaps old A region)
    float* sV = sA;
    #pragma unroll
    for (int i = 0; i < 8; i++) {
        int r = ty + 16 * i;
        #pragma unroll
        for (int j = 0; j < 4; j++) {
            int c = 2 * tx + 32 * j;
            float2 f = unpack2(acc[i][j]);
            sV[r * VSTRIDE + c]     = f.x + sB[c];
            sV[r * VSTRIDE + c + 1] = f.y + sB[c + 1];
        }
    }
    __syncthreads();

    // ---------------- attention ----------------
    // alpha_raw[r] = dot(x[node(r)], v[r]) / sqrt(128) ; 2 threads per row (64 d each)
    {
        int r = tid & 127, h = tid >> 7;
        const float* xr = sX + (r >> 4) * D_DIM + h * 64;
        const float* vr = sV + r * VSTRIDE + h * 64;
        float s = 0.f;
        #pragma unroll
        for (int d = 0; d < 64; d++) s += xr[d] * vr[d];
        sP[tid] = s;
    }
    __syncthreads();
    if (tid < 128)
        sAl[tid] = (sP[tid] + sP[tid + 128]) * 0.08838834764831845f; // 1/sqrt(128)
    __syncthreads();

    float e = 0.f;
    if (tid < 128) {
        int base = tid & ~15;
        float m = -1e30f;
        #pragma unroll
        for (int s = 0; s < 16; s++) m = fmaxf(m, sAl[base + s]);
        e = expf(sAl[tid] - m);
        sE[tid] = e;
    }
    __syncthreads();
    if (tid < 128) {
        int base = tid & ~15;
        float den = 0.f;
        #pragma unroll
        for (int s = 0; s < 16; s++) den += sE[base + s];
        sAl[tid] = e / den;
    }
    __syncthreads();

    // out[node][d] = sum_s alpha[node*16+s] * v[node*16+s][d]
    float* outp = out + ((size_t)b * N_DIM + (size_t)nc * 8) * D_DIM;
    #pragma unroll
    for (int q = 0; q < 4; q++) {
        int idx  = tid + 256 * q;        // 0..1023 = node*128 + d
        int node = idx >> 7;
        int d    = idx & 127;
        const float* vr = sV + (node * 16) * VSTRIDE + d;
        const float* al = sAl + node * 16;
        float s = 0.f;
        #pragma unroll
        for (int t2 = 0; t2 < 16; t2++) s += al[t2] * vr[t2 * VSTRIDE];
        outp[idx] = s;
    }
}

extern "C" void kernel_launch(void* const* d_in, const int* in_sizes, int n_in,
                              void* d_out, int out_size)
{
    const float* x          = (const float*)d_in[0];
    const float* x_nei_rel  = (const float*)d_in[1];
    const float* x_nei_node = (const float*)d_in[2];
    const float* W1_w       = (const float*)d_in[3];
    const float* W1_b       = (const float*)d_in[4];
    // d_in[5] is the static index i (always 0); S is compile-time 16.
    float* out = (float*)d_out;

    cudaFuncSetAttribute(nei_attention_kernel,
                         cudaFuncAttributeMaxDynamicSharedMemorySize, SMEM_BYTES);

    dim3 grid(4, B_DIM);   // 4 node-chunks x 512 batches
    nei_attention_kernel<<<grid, 256, SMEM_BYTES>>>(x, x_nei_rel, x_nei_node,
                                                    W1_w, W1_b, out);
}

// round 3
// speedup vs baseline: 2.3096x; 2.3096x over previous
#include <cuda_runtime.h>
#include <cuda_bf16.h>
#include <cstdint>

// NeiAttention via warp-level mma.sync tf32 (m16n8k8) — compiles under compute_103.
// B=512, N=32, S=16, EF=64, NF=D=128, K=192. One CTA = (batch, 8-node chunk):
//   C[128x128] = A[128x192](tf32) * W^T, then fused softmax-attention epilogue.

#define D_DIM   128
#define K_DIM   192
#define ASTRIDE 196   // A & W smem row stride (floats): bank = 4*row + col (mod 32) -> conflict-free frags
#define VSTRIDE 133

// smem layout (floats)
#define OFF_A    0        // 128*196 = 25088 (reused as sV after GEMM)
#define OFF_W    25088    // 128*196 = 25088  (W in natural [d][k] layout)
#define OFF_X    50176    // 1024
#define OFF_BIAS 51200    // 128
#define OFF_AL   51328    // 128
#define OFF_E    51456    // 128
#define OFF_P    51584    // 256
#define SMEM_FLOATS 51840
#define SMEM_BYTES  (SMEM_FLOATS * 4)   // 207,360 B

__device__ __forceinline__ uint32_t cvt_tf32(float f) {
    uint32_t o; asm("cvt.rna.tf32.f32 %0, %1;" : "=r"(o) : "f"(f)); return o;
}

__device__ __forceinline__ void mma_tf32(float d[4], uint32_t a0, uint32_t a1,
                                         uint32_t a2, uint32_t a3,
                                         uint32_t b0, uint32_t b1) {
    asm volatile(
        "mma.sync.aligned.m16n8k8.row.col.f32.tf32.tf32.f32 "
        "{%0,%1,%2,%3}, {%4,%5,%6,%7}, {%8,%9}, {%0,%1,%2,%3};"
        : "+f"(d[0]), "+f"(d[1]), "+f"(d[2]), "+f"(d[3])
        : "r"(a0), "r"(a1), "r"(a2), "r"(a3), "r"(b0), "r"(b1));
}

__global__ __launch_bounds__(256, 1)
void nei_attention_mma(const float* __restrict__ x,
                       const float* __restrict__ x_nei_rel,
                       const float* __restrict__ x_nei_node,
                       const float* __restrict__ W1_w,
                       const float* __restrict__ W1_b,
                       float* __restrict__ out)
{
    extern __shared__ float smem[];
    float* sA   = smem + OFF_A;    // A tile [row][k], tf32 bits; later reused as sV
    float* sW   = smem + OFF_W;    // W tile [d][k], tf32 bits (natural layout)
    float* sX   = smem + OFF_X;
    float* sBia = smem + OFF_BIAS;
    float* sAl  = smem + OFF_AL;
    float* sE   = smem + OFF_E;
    float* sP   = smem + OFF_P;
    float* sV   = smem + OFF_A;

    const int b   = blockIdx.y;
    const int nc  = blockIdx.x;
    const int tid = threadIdx.x;
    const int wid = tid >> 5;
    const int lid = tid & 31;
    const int g   = lid >> 2;      // groupID 0..7
    const int t   = lid & 3;       // thread-in-group 0..3
    const int wm  = wid >> 2;      // 0..1  (64 rows)
    const int wn  = wid & 3;       // 0..3  (32 cols)

    // ---------------- stage inputs (fp32 -> tf32 rna) ----------------
    {
        const size_t row0 = ((size_t)b * 512 + (size_t)nc * 128);
        const float4* rel = (const float4*)(x_nei_rel + row0 * 64);
        #pragma unroll
        for (int it = 0; it < 8; it++) {               // 2048 float4: k 0..63
            int idx = tid + it * 256;
            int r = idx >> 4, c = idx & 15;
            float4 v = rel[r * 16 + c];
            uint32_t* d = (uint32_t*)(sA + r * ASTRIDE + c * 4);
            d[0] = cvt_tf32(v.x); d[1] = cvt_tf32(v.y);
            d[2] = cvt_tf32(v.z); d[3] = cvt_tf32(v.w);
        }
        const float4* nod = (const float4*)(x_nei_node + row0 * 128);
        #pragma unroll
        for (int it = 0; it < 16; it++) {              // 4096 float4: k 64..191
            int idx = tid + it * 256;
            int r = idx >> 5, c = idx & 31;
            float4 v = nod[r * 32 + c];
            uint32_t* d = (uint32_t*)(sA + r * ASTRIDE + 64 + c * 4);
            d[0] = cvt_tf32(v.x); d[1] = cvt_tf32(v.y);
            d[2] = cvt_tf32(v.z); d[3] = cvt_tf32(v.w);
        }
        const float4* Wv = (const float4*)W1_w;        // [128 d][192 k]
        #pragma unroll
        for (int it = 0; it < 24; it++) {              // 6144 float4
            int idx = tid + it * 256;
            int dd = idx / 48, c = idx - dd * 48;
            float4 v = Wv[idx];
            uint32_t* d = (uint32_t*)(sW + dd * ASTRIDE + c * 4);
            d[0] = cvt_tf32(v.x); d[1] = cvt_tf32(v.y);
            d[2] = cvt_tf32(v.z); d[3] = cvt_tf32(v.w);
        }
        const float4* xv = (const float4*)(x + ((size_t)b * 32 + (size_t)nc * 8) * 128);
        { float4 v = xv[tid]; *(float4*)(sX + tid * 4) = v; }
        if (tid < 128) sBia[tid] = W1_b[tid];
    }
    __syncthreads();

    // ---------------- GEMM: warp tile 64x32, mma m16n8k8 tf32 ----------------
    float acc[4][4][4];
    #pragma unroll
    for (int i = 0; i < 4; i++)
        #pragma unroll
        for (int j = 0; j < 4; j++)
            #pragma unroll
            for (int q = 0; q < 4; q++) acc[i][j][q] = 0.f;

    // A frag base: row = wm*64 + i*16 + g (+8), col = kk + t (+4)
    const uint32_t* aBase = (const uint32_t*)(sA + (wm * 64 + g) * ASTRIDE + t);
    // B frag: W[n][k]: n = wn*32 + j*8 + g, k = kk + t (+4)
    const uint32_t* bBase = (const uint32_t*)(sW + (wn * 32 + g) * ASTRIDE + t);

    #pragma unroll 2
    for (int kk = 0; kk < K_DIM; kk += 8) {
        uint32_t bf[4][2];
        #pragma unroll
        for (int j = 0; j < 4; j++) {
            const uint32_t* p = bBase + j * 8 * ASTRIDE + kk;
            bf[j][0] = p[0];
            bf[j][1] = p[4];
        }
        #pragma unroll
        for (int i = 0; i < 4; i++) {
            const uint32_t* p = aBase + i * 16 * ASTRIDE + kk;
            uint32_t a0 = p[0];
            uint32_t a1 = p[8 * ASTRIDE];
            uint32_t a2 = p[4];
            uint32_t a3 = p[8 * ASTRIDE + 4];
            #pragma unroll
            for (int j = 0; j < 4; j++)
                mma_tf32(acc[i][j], a0, a1, a2, a3, bf[j][0], bf[j][1]);
        }
    }
    __syncthreads();   // all warps done reading sA -> safe to overwrite with sV

    // ---------------- epilogue: bias add, write v tile ----------------
    #pragma unroll
    for (int i = 0; i < 4; i++) {
        int row0 = wm * 64 + i * 16 + g;
        #pragma unroll
        for (int j = 0; j < 4; j++) {
            int col = wn * 32 + j * 8 + 2 * t;
            float b0 = sBia[col], b1 = sBia[col + 1];
            sV[row0 * VSTRIDE + col]           = acc[i][j][0] + b0;
            sV[row0 * VSTRIDE + col + 1]       = acc[i][j][1] + b1;
            sV[(row0 + 8) * VSTRIDE + col]     = acc[i][j][2] + b0;
            sV[(row0 + 8) * VSTRIDE + col + 1] = acc[i][j][3] + b1;
        }
    }
    __syncthreads();

    // ---------------- attention: alpha = softmax(x.v / sqrt(128)) over S=16 ----------------
    {
        int r = tid & 127, h = tid >> 7;
        const float* xr = sX + (r >> 4) * D_DIM + h * 64;
        const float* vr = sV + r * VSTRIDE + h * 64;
        float s = 0.f;
        #pragma unroll
        for (int d = 0; d < 64; d++) s += xr[d] * vr[d];
        sP[tid] = s;
    }
    __syncthreads();
    if (tid < 128)
        sAl[tid] = (sP[tid] + sP[tid + 128]) * 0.08838834764831845f;
    __syncthreads();

    float e = 0.f;
    if (tid < 128) {
        int base = tid & ~15;
        float m = -1e30f;
        #pragma unroll
        for (int s = 0; s < 16; s++) m = fmaxf(m, sAl[base + s]);
        e = expf(sAl[tid] - m);
        sE[tid] = e;
    }
    __syncthreads();
    if (tid < 128) {
        int base = tid & ~15;
        float den = 0.f;
        #pragma unroll
        for (int s = 0; s < 16; s++) den += sE[base + s];
        sAl[tid] = e / den;
    }
    __syncthreads();

    // ---------------- out[node][d] = sum_s alpha * v ----------------
    float* outp = out + ((size_t)b * 32 + (size_t)nc * 8) * D_DIM;
    #pragma unroll
    for (int q = 0; q < 4; q++) {
        int idx  = tid + 256 * q;
        int node = idx >> 7;
        int d    = idx & 127;
        const float* vr = sV + (node * 16) * VSTRIDE + d;
        const float* al = sAl + node * 16;
        float s = 0.f;
        #pragma unroll
        for (int t2 = 0; t2 < 16; t2++) s += al[t2] * vr[t2 * VSTRIDE];
        outp[idx] = s;
    }
}

extern "C" void kernel_launch(void* const* d_in, const int* in_sizes, int n_in,
                              void* d_out, int out_size)
{
    const float* x          = (const float*)d_in[0];
    const float* x_nei_rel  = (const float*)d_in[1];
    const float* x_nei_node = (const float*)d_in[2];
    const float* W1_w       = (const float*)d_in[3];
    const float* W1_b       = (const float*)d_in[4];
    float* out = (float*)d_out;

    cudaFuncSetAttribute(nei_attention_mma,
                         cudaFuncAttributeMaxDynamicSharedMemorySize, SMEM_BYTES);

    dim3 grid(4, 512);
    nei_attention_mma<<<grid, 256, SMEM_BYTES>>>(x, x_nei_rel, x_nei_node, W1_w, W1_b, out);
}

// round 4
// speedup vs baseline: 3.2430x; 1.4041x over previous
#include <cuda_runtime.h>
#include <cstdint>

// NeiAttention, persistent tcgen-legacy (mma.sync tf32) version.
// B=512,N=32,S=16,EF=64,NF=D=128,K=192. tile = (batch,8-node chunk) = 128 GEMM rows.
// 148 persistent CTAs x 256 thr; W resident in smem; A double-buffered K-halves via cp.async;
// attention epilogue entirely in registers + tiny smem reductions.

#define NTILES 2048
#define NCTAS  148
#define WST    196     // W smem row stride (floats)  -> conflict-free frag pattern
#define AST    100     // A smem row stride (floats)  -> bank = 4g+t, conflict-free

// smem layout (floats)
#define OFF_W    0        // 128*196 = 25088
#define OFF_A0   25088    // 128*100 = 12800
#define OFF_A1   37888    // 12800
#define OFF_X    50688    // 2 x 1024 (double-buffered x rows)
#define OFF_PART 52736    // 512  (4 wn x 128 logit partials)
#define OFF_AL   53248    // 128
#define OFF_E    53376    // 128
#define OFF_BIA  53504    // 128
#define SMEM_FLOATS 53632
#define SMEM_BYTES  (SMEM_FLOATS * 4)   // 214,528 B

__device__ __forceinline__ uint32_t smem_u32(const void* p) {
    uint32_t a;
    asm("{ .reg .u64 t; cvta.to.shared.u64 t, %1; cvt.u32.u64 %0, t; }" : "=r"(a) : "l"(p));
    return a;
}
__device__ __forceinline__ uint32_t cvt_tf32(float f) {
    uint32_t o; asm("cvt.rna.tf32.f32 %0, %1;" : "=r"(o) : "f"(f)); return o;
}
__device__ __forceinline__ void mma_tf32(float d[4], uint32_t a0, uint32_t a1,
                                         uint32_t a2, uint32_t a3,
                                         uint32_t b0, uint32_t b1) {
    asm volatile(
        "mma.sync.aligned.m16n8k8.row.col.f32.tf32.tf32.f32 "
        "{%0,%1,%2,%3}, {%4,%5,%6,%7}, {%8,%9}, {%0,%1,%2,%3};"
        : "+f"(d[0]), "+f"(d[1]), "+f"(d[2]), "+f"(d[3])
        : "r"(a0), "r"(a1), "r"(a2), "r"(a3), "r"(b0), "r"(b1));
}
__device__ __forceinline__ void cpa16(uint32_t dst, const void* src) {
    asm volatile("cp.async.cg.shared.global [%0], [%1], 16;" :: "r"(dst), "l"(src));
}
__device__ __forceinline__ void cp_commit() { asm volatile("cp.async.commit_group;" ::: "memory"); }
__device__ __forceinline__ void cp_wait_all() { asm volatile("cp.async.wait_group 0;" ::: "memory"); }
__device__ __forceinline__ float shflx(float v, int m) {
    return __shfl_xor_sync(0xffffffffu, v, m);
}

// ---- staging: raw fp32 via cp.async ----
// half0 of a tile: k 0..95  = rel[0..63] + nod cols 0..31(k 64..95)
__device__ __forceinline__ void stage_h0(uint32_t aU, const float* __restrict__ rel,
                                         const float* __restrict__ nod, int tile, int tid) {
    const float4* rp = (const float4*)(rel + (size_t)tile * 8192);    // 128 rows x 64
    #pragma unroll
    for (int it = 0; it < 8; it++) {
        int idx = tid + it * 256;
        int r = idx >> 4, c = idx & 15;
        cpa16(aU + (uint32_t)(r * AST + c * 4) * 4u, rp + r * 16 + c);
    }
    const float4* np = (const float4*)(nod + (size_t)tile * 16384);   // 128 rows x 128
    #pragma unroll
    for (int it = 0; it < 4; it++) {
        int idx = tid + it * 256;
        int r = idx >> 3, c = idx & 7;                                // nod k 0..31 -> klocal 64..95
        cpa16(aU + (uint32_t)(r * AST + 64 + c * 4) * 4u, np + r * 32 + c);
    }
}
// half1 of a tile: k 96..191 = nod cols 32..127 (float4 cols 8..31)
__device__ __forceinline__ void stage_h1(uint32_t aU, const float* __restrict__ nod,
                                         int tile, int tid) {
    const float4* np = (const float4*)(nod + (size_t)tile * 16384);
    #pragma unroll
    for (int it = 0; it < 12; it++) {
        int idx = tid + it * 256;                                     // 0..3071
        int r = idx / 24, c = idx - r * 24;
        cpa16(aU + (uint32_t)(r * AST + c * 4) * 4u, np + r * 32 + 8 + c);
    }
}
__device__ __forceinline__ void stage_x(uint32_t xU, const float* __restrict__ x,
                                        int tile, int par, int tid) {
    cpa16(xU + (uint32_t)(par * 1024 + tid * 4) * 4u,
          (const float4*)(x + (size_t)tile * 1024) + tid);
}

// ---- GEMM over one K-half (96), cvt.rna at fragment load ----
__device__ __forceinline__ void compute_half(float acc[4][4][4],
                                             const float* __restrict__ aBuf,
                                             const float* __restrict__ sW,
                                             int h, int wm, int wn, int g, int t4) {
    const float*    aBase = aBuf + (wm * 64 + g) * AST + t4;
    const uint32_t* bBase = (const uint32_t*)(sW + (wn * 32 + g) * WST + h * 96 + t4);
    #pragma unroll 4
    for (int kk = 0; kk < 96; kk += 8) {
        uint32_t bf0[4], bf1[4];
        #pragma unroll
        for (int j = 0; j < 4; j++) {
            const uint32_t* p = bBase + j * (8 * WST) + kk;
            bf0[j] = p[0];
            bf1[j] = p[4];
        }
        #pragma unroll
        for (int i = 0; i < 4; i++) {
            const float* p = aBase + i * (16 * AST) + kk;
            uint32_t a0 = cvt_tf32(p[0]);
            uint32_t a1 = cvt_tf32(p[8 * AST]);
            uint32_t a2 = cvt_tf32(p[4]);
            uint32_t a3 = cvt_tf32(p[8 * AST + 4]);
            #pragma unroll
            for (int j = 0; j < 4; j++)
                mma_tf32(acc[i][j], a0, a1, a2, a3, bf0[j], bf1[j]);
        }
    }
}

__global__ __launch_bounds__(256, 1)
void nei_attention_pers(const float* __restrict__ x,
                        const float* __restrict__ x_nei_rel,
                        const float* __restrict__ x_nei_node,
                        const float* __restrict__ W1_w,
                        const float* __restrict__ W1_b,
                        float* __restrict__ out)
{
    extern __shared__ float smem[];
    const uint32_t sb = smem_u32(smem);
    float* sW    = smem + OFF_W;
    float* sA0   = smem + OFF_A0;
    float* sA1   = smem + OFF_A1;
    float* sX    = smem + OFF_X;
    float* sPart = smem + OFF_PART;
    float* sAl   = smem + OFF_AL;
    float* sE    = smem + OFF_E;
    float* sBia  = smem + OFF_BIA;
    const uint32_t aU0 = sb + OFF_A0 * 4, aU1 = sb + OFF_A1 * 4, xU = sb + OFF_X * 4;

    const int tid = threadIdx.x;
    const int wid = tid >> 5, lid = tid & 31;
    const int g = lid >> 2, t4 = lid & 3;
    const int wm = wid >> 2, wn = wid & 3;
    const int bid = blockIdx.x;

    // ---- stage W (tf32) + bias once ----
    {
        const float4* Wv = (const float4*)W1_w;        // [128 d][192 k]
        #pragma unroll
        for (int it = 0; it < 24; it++) {
            int idx = tid + it * 256;
            int dd = idx / 48, c = idx - dd * 48;
            float4 v = Wv[idx];
            uint32_t* dp = (uint32_t*)(sW + dd * WST + c * 4);
            dp[0] = cvt_tf32(v.x); dp[1] = cvt_tf32(v.y);
            dp[2] = cvt_tf32(v.z); dp[3] = cvt_tf32(v.w);
        }
        if (tid < 128) sBia[tid] = W1_b[tid];
    }

    // ---- prologue: stage first tile's half0 + x ----
    stage_h0(aU0, x_nei_rel, x_nei_node, bid, tid);
    stage_x(xU, x, bid, 0, tid);
    cp_commit();

    int par = 0;
    for (int tile = bid; tile < NTILES; tile += NCTAS) {
        float acc[4][4][4];
        #pragma unroll
        for (int i = 0; i < 4; i++)
            #pragma unroll
            for (int j = 0; j < 4; j++)
                #pragma unroll
                for (int q = 0; q < 4; q++) acc[i][j][q] = 0.f;

        // -------- half 0 --------
        cp_wait_all();
        __syncthreads();                       // half0 data (+W on first iter) visible
        stage_h1(aU1, x_nei_node, tile, tid);  // overlap: load half1 during compute
        cp_commit();
        compute_half(acc, sA0, sW, 0, wm, wn, g, t4);

        // -------- half 1 --------
        cp_wait_all();
        __syncthreads();
        {
            int tn = tile + NCTAS;
            if (tn < NTILES) {                 // overlap: next tile's half0 + x
                stage_h0(aU0, x_nei_rel, x_nei_node, tn, tid);
                stage_x(xU, x, tn, par ^ 1, tid);
            }
        }
        cp_commit();
        compute_half(acc, sA1, sW, 1, wm, wn, g, t4);

        // -------- epilogue: attention from registers --------
        // logits (bias-free: softmax invariant to +x.b)
        const float* xb = sX + par * 1024;
        #pragma unroll
        for (int i = 0; i < 4; i++) {
            float lo = 0.f, hi = 0.f;
            #pragma unroll
            for (int j = 0; j < 4; j++) {
                const float2 xv = *(const float2*)(xb + (wm * 4 + i) * 128 + wn * 32 + j * 8 + 2 * t4);
                lo += xv.x * acc[i][j][0] + xv.y * acc[i][j][1];
                hi += xv.x * acc[i][j][2] + xv.y * acc[i][j][3];
            }
            lo += shflx(lo, 1); lo += shflx(lo, 2);   // reduce over t4
            hi += shflx(hi, 1); hi += shflx(hi, 2);
            if (t4 == 0) {
                int r = wm * 64 + i * 16 + g;
                sPart[wn * 128 + r]     = lo;
                sPart[wn * 128 + r + 8] = hi;
            }
        }
        __syncthreads();
        float e = 0.f;
        if (tid < 128) {
            float raw = (sPart[tid] + sPart[128 + tid] + sPart[256 + tid] + sPart[384 + tid])
                        * 0.08838834764831845f;       // 1/sqrt(128)
            sAl[tid] = raw;
        }
        __syncthreads();
        if (tid < 128) {
            int base = tid & ~15;
            float m = -1e30f;
            #pragma unroll
            for (int s = 0; s < 16; s++) m = fmaxf(m, sAl[base + s]);
            e = expf(sAl[tid] - m);
            sE[tid] = e;
        }
        __syncthreads();
        if (tid < 128) {
            int base = tid & ~15;
            float den = 0.f;
            #pragma unroll
            for (int s = 0; s < 16; s++) den += sE[base + s];
            sAl[tid] = e / den;
        }
        __syncthreads();

        // out[node][col] = sum_s alpha * C  (+ bias, since sum alpha = 1)
        float* outp = out + (size_t)tile * 1024;
        #pragma unroll
        for (int i = 0; i < 4; i++) {
            int r = wm * 64 + i * 16 + g;
            float alo = sAl[r], ahi = sAl[r + 8];
            #pragma unroll
            for (int j = 0; j < 4; j++) {
                float o0 = alo * acc[i][j][0] + ahi * acc[i][j][2];
                float o1 = alo * acc[i][j][1] + ahi * acc[i][j][3];
                o0 += shflx(o0, 4); o0 += shflx(o0, 8); o0 += shflx(o0, 16);  // sum over g
                o1 += shflx(o1, 4); o1 += shflx(o1, 8); o1 += shflx(o1, 16);
                if (lid < 4) {                  // g == 0 lanes hold the sums
                    int col  = wn * 32 + j * 8 + 2 * t4;
                    int node = wm * 4 + i;
                    float2 w;
                    w.x = o0 + sBia[col];
                    w.y = o1 + sBia[col + 1];
                    *(float2*)(outp + node * 128 + col) = w;
                }
            }
        }
        par ^= 1;
    }
}

extern "C" void kernel_launch(void* const* d_in, const int* in_sizes, int n_in,
                              void* d_out, int out_size)
{
    const float* x          = (const float*)d_in[0];
    const float* x_nei_rel  = (const float*)d_in[1];
    const float* x_nei_node = (const float*)d_in[2];
    const float* W1_w       = (const float*)d_in[3];
    const float* W1_b       = (const float*)d_in[4];
    float* out = (float*)d_out;

    cudaFuncSetAttribute(nei_attention_pers,
                         cudaFuncAttributeMaxDynamicSharedMemorySize, SMEM_BYTES);

    nei_attention_pers<<<NCTAS, 256, SMEM_BYTES>>>(x, x_nei_rel, x_nei_node, W1_w, W1_b, out);
}